// round 15
// baseline (speedup 1.0000x reference)
#include <cuda_runtime.h>
#include <cuda_bf16.h>
#include <math.h>
#include <stdint.h>

// Problem constants
#define LL 1024
#define BB 4
#define DD 1024
#define HH 16
#define HDIM 64
#define DFF_ 4096
#define NROWS 4096        // L*B
#define QKVW 3072         // 3*D

// ---------------- scratch (device globals; no allocation allowed) ------------
__device__ __nv_bfloat16 g_h_hi[(size_t)NROWS * DD],  g_h_lo[(size_t)NROWS * DD];
__device__ __nv_bfloat16 g_qkv_hi[(size_t)NROWS * QKVW], g_qkv_lo[(size_t)NROWS * QKVW];
__device__ __nv_bfloat16 g_attn_hi[(size_t)NROWS * DD], g_attn_lo[(size_t)NROWS * DD];
__device__ float         g_x1[(size_t)NROWS * DD];
__device__ __nv_bfloat16 g_h2_hi[(size_t)NROWS * DD], g_h2_lo[(size_t)NROWS * DD];
__device__ __nv_bfloat16 g_ff_hi[(size_t)NROWS * DFF_], g_ff_lo[(size_t)NROWS * DFF_];
__device__ __nv_bfloat16 g_w1_hi[(size_t)QKVW * DD], g_w1_lo[(size_t)QKVW * DD];
__device__ __nv_bfloat16 g_w2_hi[(size_t)DD * DD],   g_w2_lo[(size_t)DD * DD];
__device__ __nv_bfloat16 g_w3_hi[(size_t)DFF_ * DD], g_w3_lo[(size_t)DFF_ * DD];
__device__ __nv_bfloat16 g_w4_hi[(size_t)DD * DFF_], g_w4_lo[(size_t)DD * DFF_];

// ---------------- helpers ----------------------------------------------------
__device__ __forceinline__ uint32_t smem_u32(const void* p) {
    uint32_t a;
    asm("{ .reg .u64 t; cvta.to.shared.u64 t, %1; cvt.u32.u64 %0, t; }" : "=r"(a) : "l"(p));
    return a;
}
#define SWZ128(o) ((o) ^ (((o) >> 3) & 0x70))
#define SWZ64(o)  ((o) ^ (((o) >> 3) & 0x30))

#define CP16(s, g) asm volatile("cp.async.cg.shared.global [%0], [%1], 16;\n" :: "r"(s), "l"(g) : "memory")
#define CP_COMMIT() asm volatile("cp.async.commit_group;\n" ::: "memory")
#define CP_WAIT1()  asm volatile("cp.async.wait_group 1;\n" ::: "memory")
#define CP_WAIT0()  asm volatile("cp.async.wait_group 0;\n" ::: "memory")

#define LDSM4(r, addr) \
    asm volatile("ldmatrix.sync.aligned.m8n8.x4.shared.b16 {%0,%1,%2,%3}, [%4];" \
        : "=r"((r)[0]), "=r"((r)[1]), "=r"((r)[2]), "=r"((r)[3]) : "r"(addr))
#define LDSM4T(r, addr) \
    asm volatile("ldmatrix.sync.aligned.m8n8.x4.trans.shared.b16 {%0,%1,%2,%3}, [%4];" \
        : "=r"((r)[0]), "=r"((r)[1]), "=r"((r)[2]), "=r"((r)[3]) : "r"(addr))

#define MMA16816(d, a, b0, b1) \
    asm volatile("mma.sync.aligned.m16n8k16.row.col.f32.bf16.bf16.f32 " \
        "{%0,%1,%2,%3}, {%4,%5,%6,%7}, {%8,%9}, {%0,%1,%2,%3};" \
        : "+f"((d)[0]), "+f"((d)[1]), "+f"((d)[2]), "+f"((d)[3]) \
        : "r"((a)[0]), "r"((a)[1]), "r"((a)[2]), "r"((a)[3]), "r"(b0), "r"(b1))

__device__ __forceinline__ void split2(float v, __nv_bfloat16& h, __nv_bfloat16& l) {
    h = __float2bfloat16(v);
    l = __float2bfloat16(v - __bfloat162float(h));
}
__device__ __forceinline__ void pack_split(float a, float b, uint32_t& hi, uint32_t& lo) {
    __nv_bfloat162 h = __floats2bfloat162_rn(a, b);
    hi = *reinterpret_cast<uint32_t*>(&h);
    __nv_bfloat162 l = __floats2bfloat162_rn(a - __bfloat162float(h.x), b - __bfloat162float(h.y));
    lo = *reinterpret_cast<uint32_t*>(&l);
}

// ---------------- merged weight split: fp32 -> bf16 hi/lo, all 4 weights -----
#define W1N (QKVW * DD)
#define W2N (DD * DD)
#define W3N (DFF_ * DD)
#define W4N (DD * DFF_)
__global__ void split_all_kernel(const float* __restrict__ s1, const float* __restrict__ s2,
                                 const float* __restrict__ s3, const float* __restrict__ s4,
                                 __nv_bfloat16* __restrict__ h1, __nv_bfloat16* __restrict__ l1,
                                 __nv_bfloat16* __restrict__ h2, __nv_bfloat16* __restrict__ l2,
                                 __nv_bfloat16* __restrict__ h3, __nv_bfloat16* __restrict__ l3,
                                 __nv_bfloat16* __restrict__ h4, __nv_bfloat16* __restrict__ l4) {
    int i = (blockIdx.x * 256 + threadIdx.x) * 4;
    const float* src; __nv_bfloat16 *hi, *lo;
    if (i < W1N)                   { src = s1; hi = h1; lo = l1; }
    else if (i < W1N + W2N)        { i -= W1N; src = s2; hi = h2; lo = l2; }
    else if (i < W1N + W2N + W3N)  { i -= W1N + W2N; src = s3; hi = h3; lo = l3; }
    else                           { i -= W1N + W2N + W3N; src = s4; hi = h4; lo = l4; }
    float4 v = *(const float4*)(src + i);
    __nv_bfloat16 a0, b0, a1, b1, a2, b2, a3, b3;
    split2(v.x, a0, b0); split2(v.y, a1, b1); split2(v.z, a2, b2); split2(v.w, a3, b3);
    *(__nv_bfloat162*)&hi[i]     = __nv_bfloat162(a0, a1);
    *(__nv_bfloat162*)&hi[i + 2] = __nv_bfloat162(a2, a3);
    *(__nv_bfloat162*)&lo[i]     = __nv_bfloat162(b0, b1);
    *(__nv_bfloat162*)&lo[i + 2] = __nv_bfloat162(b2, b3);
}

// ---------------- LayerNorm -> bf16 hi/lo ------------------------------------
__global__ void ln_split_kernel(const float* __restrict__ X, const float* __restrict__ w,
                                const float* __restrict__ b,
                                __nv_bfloat16* __restrict__ Yhi, __nv_bfloat16* __restrict__ Ylo) {
    int row = blockIdx.x;
    int tid = threadIdx.x;
    const float* xr = X + (size_t)row * DD;
    float v0 = xr[tid], v1 = xr[tid + 256], v2 = xr[tid + 512], v3 = xr[tid + 768];
    float s = v0 + v1 + v2 + v3;
    float s2 = v0 * v0 + v1 * v1 + v2 * v2 + v3 * v3;
    #pragma unroll
    for (int off = 16; off; off >>= 1) {
        s  += __shfl_xor_sync(0xffffffffu, s, off);
        s2 += __shfl_xor_sync(0xffffffffu, s2, off);
    }
    __shared__ float sh[16];
    __shared__ float smean, sinv;
    int wid = tid >> 5, lid = tid & 31;
    if (lid == 0) { sh[wid] = s; sh[wid + 8] = s2; }
    __syncthreads();
    if (wid == 0) {
        float a  = (lid < 8) ? sh[lid] : 0.f;
        float a2 = (lid < 8) ? sh[lid + 8] : 0.f;
        #pragma unroll
        for (int off = 4; off; off >>= 1) {
            a  += __shfl_xor_sync(0xffffffffu, a, off, 8);
            a2 += __shfl_xor_sync(0xffffffffu, a2, off, 8);
        }
        if (lid == 0) {
            float mean = a * (1.f / DD);
            float var = a2 * (1.f / DD) - mean * mean;
            smean = mean;
            sinv = rsqrtf(var + 1e-5f);
        }
    }
    __syncthreads();
    float mean = smean, inv = sinv;
    size_t base = (size_t)row * DD;
    #pragma unroll
    for (int q = 0; q < 4; q++) {
        int c = tid + q * 256;
        float v = (q == 0 ? v0 : q == 1 ? v1 : q == 2 ? v2 : v3);
        float y = (v - mean) * inv * w[c] + b[c];
        __nv_bfloat16 h, l;
        split2(y, h, l);
        Yhi[base + c] = h;
        Ylo[base + c] = l;
    }
}

// ---------------- mma.sync split-bf16 GEMM, CTA 128x128, chunk 32, 2 CTA/SM --
// EPI: 1 = gelu(+bias) -> hi/lo ; 2 = +bias+Res -> OutF ; 3 = +bias -> hi/lo
// Per-chunk smem (32-K): Ahi 8K | Alo 8K | Bhi 8K | Blo 8K = 32K; 2 buffers = 64K.
#define GB_STRIDE 32768
__global__ void __launch_bounds__(256, 2)
gemm_mma(const __nv_bfloat16* __restrict__ Ahi, const __nv_bfloat16* __restrict__ Alo,
         const __nv_bfloat16* __restrict__ Bhi, const __nv_bfloat16* __restrict__ Blo,
         const float* __restrict__ bias, const float* __restrict__ Res,
         float* __restrict__ OutF, __nv_bfloat16* __restrict__ OutHi,
         __nv_bfloat16* __restrict__ OutLo, int M, int N, int K, int EPI) {
    extern __shared__ __align__(1024) char smem[];
    uint32_t sb = smem_u32(smem);
    int tid = threadIdx.x;
    int w = tid >> 5, lane = tid & 31;
    int wm = w & 3, wn = w >> 2;            // 4 m-strips(32) x 2 n-strips(64)
    int m0 = blockIdx.y * 128, n0 = blockIdx.x * 128;
    const int nc = K >> 5;

    float acc[2][8][4];
    #pragma unroll
    for (int i = 0; i < 2; i++)
        #pragma unroll
        for (int j = 0; j < 8; j++)
            #pragma unroll
            for (int r = 0; r < 4; r++) acc[i][j][r] = 0.f;

    int rowA = (lane & 7) + (((lane >> 3) & 1) << 3);
    int kbA  = ((lane >> 4) & 1) << 4;
    int rowB = (lane & 7) + (((lane >> 4) & 1) << 3);
    int kbB  = ((lane >> 3) & 1) << 4;

    // chunk loader: 128x32 A (hi,lo) + 128x32 B (hi,lo); 64B rows, SW64 swizzle
    #define GLOAD(buf, k0)                                                       \
    {                                                                            \
        uint32_t bA = sb + (buf) * GB_STRIDE;                                    \
        _Pragma("unroll")                                                        \
        for (int i = 0; i < 2; i++) {                                            \
            int id = tid + (i << 8);                                             \
            int row = id >> 2, c = id & 3;                                       \
            uint32_t so = SWZ64((uint32_t)(row * 64 + c * 16));                  \
            size_t oa = (size_t)(m0 + row) * K + (k0) + c * 8;                   \
            size_t ob = (size_t)(n0 + row) * K + (k0) + c * 8;                   \
            CP16(bA + so,         Ahi + oa);                                     \
            CP16(bA +  8192 + so, Alo + oa);                                     \
            CP16(bA + 16384 + so, Bhi + ob);                                     \
            CP16(bA + 24576 + so, Blo + ob);                                     \
        }                                                                        \
    }

    GLOAD(0, 0);
    CP_COMMIT();

    for (int kc = 0; kc < nc; kc++) {
        int b = kc & 1;
        if (kc + 1 < nc) {
            if (kc >= 1) __syncthreads();
            GLOAD(b ^ 1, (kc + 1) << 5);
            CP_COMMIT();
            CP_WAIT1();
        } else {
            CP_WAIT0();
        }
        __syncthreads();

        uint32_t tb = sb + b * GB_STRIDE;
        #pragma unroll
        for (int ks = 0; ks < 2; ks++) {
            int kb = ks * 32;                  // 16 bf16 = 32 bytes per k-step
            uint32_t ah[2][4], al[2][4], bh[4][4], bl[4][4];
            #pragma unroll
            for (int mt = 0; mt < 2; mt++) {
                uint32_t off = SWZ64((uint32_t)((wm * 32 + mt * 16 + rowA) * 64 + kb + kbA));
                LDSM4(ah[mt], tb + off);
                LDSM4(al[mt], tb + 8192 + off);
            }
            #pragma unroll
            for (int p = 0; p < 4; p++) {
                uint32_t off = SWZ64((uint32_t)((wn * 64 + p * 16 + rowB) * 64 + kb + kbB));
                LDSM4(bh[p], tb + 16384 + off);
                LDSM4(bl[p], tb + 24576 + off);
            }
            #pragma unroll
            for (int mt = 0; mt < 2; mt++)
                #pragma unroll
                for (int nt = 0; nt < 8; nt++) {
                    int p = nt >> 1, h = (nt & 1) * 2;
                    MMA16816(acc[mt][nt], ah[mt], bh[p][h], bh[p][h + 1]);
                }
            #pragma unroll
            for (int mt = 0; mt < 2; mt++)
                #pragma unroll
                for (int nt = 0; nt < 8; nt++) {
                    int p = nt >> 1, h = (nt & 1) * 2;
                    MMA16816(acc[mt][nt], ah[mt], bl[p][h], bl[p][h + 1]);
                }
            #pragma unroll
            for (int mt = 0; mt < 2; mt++)
                #pragma unroll
                for (int nt = 0; nt < 8; nt++) {
                    int p = nt >> 1, h = (nt & 1) * 2;
                    MMA16816(acc[mt][nt], al[mt], bh[p][h], bh[p][h + 1]);
                }
        }
    }

    int gr = lane >> 2, tg = lane & 3;
    #pragma unroll
    for (int mt = 0; mt < 2; mt++) {
        #pragma unroll
        for (int nt = 0; nt < 8; nt++) {
            int r0 = m0 + wm * 32 + mt * 16 + gr;
            int c  = n0 + wn * 64 + nt * 8 + tg * 2;
            float b0 = __ldg(&bias[c]), b1 = __ldg(&bias[c + 1]);
            float v00 = acc[mt][nt][0] + b0, v01 = acc[mt][nt][1] + b1;
            float v10 = acc[mt][nt][2] + b0, v11 = acc[mt][nt][3] + b1;
            size_t o0 = (size_t)r0 * N + c;
            size_t o1 = (size_t)(r0 + 8) * N + c;
            if (EPI == 1 || EPI == 3) {
                if (EPI == 1) {
                    v00 = 0.5f * v00 * (1.f + erff(v00 * 0.70710678118654752f));
                    v01 = 0.5f * v01 * (1.f + erff(v01 * 0.70710678118654752f));
                    v10 = 0.5f * v10 * (1.f + erff(v10 * 0.70710678118654752f));
                    v11 = 0.5f * v11 * (1.f + erff(v11 * 0.70710678118654752f));
                }
                uint32_t hi, lo;
                pack_split(v00, v01, hi, lo);
                *(uint32_t*)&OutHi[o0] = hi;
                *(uint32_t*)&OutLo[o0] = lo;
                pack_split(v10, v11, hi, lo);
                *(uint32_t*)&OutHi[o1] = hi;
                *(uint32_t*)&OutLo[o1] = lo;
            } else {
                if (EPI == 2) {
                    float2 r0v = *(const float2*)&Res[o0];
                    float2 r1v = *(const float2*)&Res[o1];
                    v00 += r0v.x; v01 += r0v.y; v10 += r1v.x; v11 += r1v.y;
                }
                *(float2*)&OutF[o0] = make_float2(v00, v01);
                *(float2*)&OutF[o1] = make_float2(v10, v11);
            }
        }
    }
    #undef GLOAD
}

// ---------------- Flash attention, split-bf16 mma.sync, full pipeline --------
// (unchanged from R12)
#define EDGE_OFF 163840
#define EDGE_PITCH 528
__global__ void __launch_bounds__(256, 1)
attn_mma(const __nv_bfloat16* __restrict__ qh, const __nv_bfloat16* __restrict__ ql,
         const float* __restrict__ edge, float* __restrict__ edge_out,
         __nv_bfloat16* __restrict__ attn_hi, __nv_bfloat16* __restrict__ attn_lo) {
    extern __shared__ __align__(1024) char smem[];
    uint32_t sb = smem_u32(smem);
    const uint32_t QHo = 0, QLo = 16384, BUF = 32768, BUFSZ = 65536;
    int bh = blockIdx.y;
    int q0 = blockIdx.x * 128;
    int b = bh >> 4, hh = bh & 15;
    int tid = threadIdx.x, lane = tid & 31, wr = tid >> 5;
    int g = lane >> 2, tg = lane & 3;

    size_t ebase0 = ((size_t)bh << 20) + (size_t)q0 * LL;

    #pragma unroll
    for (int i = 0; i < 8; i++) {
        int id = tid + i * 256;
        int a = id >> 10;
        int r = (id >> 3) & 127, c = id & 7;
        uint32_t so = SWZ128((uint32_t)(r * 128 + c * 16));
        size_t off = ((size_t)(q0 + r) * BB + b) * QKVW + hh * HDIM + c * 8;
        CP16(sb + (a ? QLo : QHo) + so, (a ? ql : qh) + off);
    }
    #pragma unroll
    for (int i = 0; i < 16; i++) {
        int id = tid + i * 256;
        int a = id >> 10;
        int r = (id >> 3) & 127, c = id & 7;
        uint32_t so = SWZ128((uint32_t)(r * 128 + c * 16));
        size_t off = ((size_t)r * BB + b) * QKVW + hh * HDIM + c * 8 + ((a >= 2) ? 2 * DD : DD);
        CP16(sb + BUF + a * 16384 + so, ((a & 1) ? ql : qh) + off);
    }
    #pragma unroll
    for (int i = 0; i < 16; i++) {
        int id = tid + i * 256;
        int r = id >> 5, c = id & 31;
        CP16(sb + EDGE_OFF + r * EDGE_PITCH + c * 16, edge + ebase0 + (size_t)r * LL + c * 4);
    }
    CP_COMMIT(); CP_WAIT0(); __syncthreads();

    int rowA = (lane & 7) + (((lane >> 3) & 1) << 3);
    int kbA  = ((lane >> 4) & 1) << 4;
    uint32_t qa_h[4][4], qa_l[4][4];
    #pragma unroll
    for (int ks = 0; ks < 4; ks++) {
        uint32_t off = SWZ128((uint32_t)((wr * 16 + rowA) * 128 + ks * 32 + kbA));
        LDSM4(qa_h[ks], sb + QHo + off);
        LDSM4(qa_l[ks], sb + QLo + off);
    }

    float m_run[2] = {-1e30f, -1e30f}, l_run[2] = {0.f, 0.f};
    float Oacc[8][4];
    #pragma unroll
    for (int i = 0; i < 8; i++)
        #pragma unroll
        for (int r = 0; r < 4; r++) Oacc[i][r] = 0.f;

    int rowB = (lane & 7) + (((lane >> 4) & 1) << 3);
    int kbB  = ((lane >> 3) & 1) << 4;
    int rowV = lane & 15, dcV = ((lane >> 4) & 1) * 8;
    int erow = (wr * 16 + g) * EDGE_PITCH + tg * 8;

    for (int kt = 0; kt < 8; kt++) {
        int bf = kt & 1;
        if (kt > 0) { CP_WAIT0(); }
        __syncthreads();

        if (kt + 1 < 8) {
            int k0n = (kt + 1) * 128;
            uint32_t dstb = sb + BUF + (bf ^ 1) * BUFSZ;
            #pragma unroll
            for (int i = 0; i < 16; i++) {
                int id = tid + i * 256;
                int a = id >> 10;
                int r = (id >> 3) & 127, c = id & 7;
                uint32_t so = SWZ128((uint32_t)(r * 128 + c * 16));
                size_t off = ((size_t)(k0n + r) * BB + b) * QKVW + hh * HDIM + c * 8
                           + ((a >= 2) ? 2 * DD : DD);
                CP16(dstb + a * 16384 + so, ((a & 1) ? ql : qh) + off);
            }
            CP_COMMIT();
        }

        uint32_t tb = sb + BUF + bf * BUFSZ;
        int k0 = kt * 128;

        float S[16][4];
        #pragma unroll
        for (int i = 0; i < 16; i++)
            #pragma unroll
            for (int r = 0; r < 4; r++) S[i][r] = 0.f;
        #pragma unroll
        for (int ks = 0; ks < 4; ks++) {
            #pragma unroll
            for (int jp = 0; jp < 4; jp++) {
                uint32_t kh0[4], kl0[4], kh1[4], kl1[4];
                uint32_t off0 = SWZ128((uint32_t)(((2 * jp) * 16 + rowB) * 128 + ks * 32 + kbB));
                uint32_t off1 = SWZ128((uint32_t)(((2 * jp + 1) * 16 + rowB) * 128 + ks * 32 + kbB));
                LDSM4(kh0, tb + off0); LDSM4(kl0, tb + 16384 + off0);
                LDSM4(kh1, tb + off1); LDSM4(kl1, tb + 16384 + off1);
                MMA16816(S[4 * jp],     qa_h[ks], kh0[0], kh0[1]);
                MMA16816(S[4 * jp + 1], qa_h[ks], kh0[2], kh0[3]);
                MMA16816(S[4 * jp + 2], qa_h[ks], kh1[0], kh1[1]);
                MMA16816(S[4 * jp + 3], qa_h[ks], kh1[2], kh1[3]);
                MMA16816(S[4 * jp],     qa_h[ks], kl0[0], kl0[1]);
                MMA16816(S[4 * jp + 1], qa_h[ks], kl0[2], kl0[3]);
                MMA16816(S[4 * jp + 2], qa_h[ks], kl1[0], kl1[1]);
                MMA16816(S[4 * jp + 3], qa_h[ks], kl1[2], kl1[3]);
                MMA16816(S[4 * jp],     qa_l[ks], kh0[0], kh0[1]);
                MMA16816(S[4 * jp + 1], qa_l[ks], kh0[2], kh0[3]);
                MMA16816(S[4 * jp + 2], qa_l[ks], kh1[0], kh1[1]);
                MMA16816(S[4 * jp + 3], qa_l[ks], kh1[2], kh1[3]);
            }
        }

        size_t ebase = ((size_t)bh << 20) + (size_t)(q0 + wr * 16 + g) * LL + k0 + tg * 2;
        #pragma unroll
        for (int nt = 0; nt < 16; nt++) {
            float2 ea = *(const float2*)(smem + EDGE_OFF + erow + nt * 32);
            float2 eb = *(const float2*)(smem + EDGE_OFF + erow + nt * 32 + 8 * EDGE_PITCH);
            S[nt][0] = fmaf(S[nt][0], 0.125f, ea.x);
            S[nt][1] = fmaf(S[nt][1], 0.125f, ea.y);
            S[nt][2] = fmaf(S[nt][2], 0.125f, eb.x);
            S[nt][3] = fmaf(S[nt][3], 0.125f, eb.y);
            size_t e0 = ebase + nt * 8;
            *(float2*)&edge_out[e0]          = make_float2(S[nt][0], S[nt][1]);
            *(float2*)&edge_out[e0 + 8 * LL] = make_float2(S[nt][2], S[nt][3]);
        }

        float mx0 = -1e30f, mx1 = -1e30f;
        #pragma unroll
        for (int nt = 0; nt < 16; nt++) {
            mx0 = fmaxf(mx0, fmaxf(S[nt][0], S[nt][1]));
            mx1 = fmaxf(mx1, fmaxf(S[nt][2], S[nt][3]));
        }
        mx0 = fmaxf(mx0, __shfl_xor_sync(0xffffffffu, mx0, 1));
        mx0 = fmaxf(mx0, __shfl_xor_sync(0xffffffffu, mx0, 2));
        mx1 = fmaxf(mx1, __shfl_xor_sync(0xffffffffu, mx1, 1));
        mx1 = fmaxf(mx1, __shfl_xor_sync(0xffffffffu, mx1, 2));
        float mn0 = fmaxf(m_run[0], mx0), mn1 = fmaxf(m_run[1], mx1);
        float corr0 = __expf(m_run[0] - mn0), corr1 = __expf(m_run[1] - mn1);
        float s0 = 0.f, s1 = 0.f;
        #pragma unroll
        for (int nt = 0; nt < 16; nt++) {
            S[nt][0] = __expf(S[nt][0] - mn0); s0 += S[nt][0];
            S[nt][1] = __expf(S[nt][1] - mn0); s0 += S[nt][1];
            S[nt][2] = __expf(S[nt][2] - mn1); s1 += S[nt][2];
            S[nt][3] = __expf(S[nt][3] - mn1); s1 += S[nt][3];
        }
        s0 += __shfl_xor_sync(0xffffffffu, s0, 1);
        s0 += __shfl_xor_sync(0xffffffffu, s0, 2);
        s1 += __shfl_xor_sync(0xffffffffu, s1, 1);
        s1 += __shfl_xor_sync(0xffffffffu, s1, 2);
        l_run[0] = l_run[0] * corr0 + s0; m_run[0] = mn0;
        l_run[1] = l_run[1] * corr1 + s1; m_run[1] = mn1;
        #pragma unroll
        for (int nt = 0; nt < 8; nt++) {
            Oacc[nt][0] *= corr0; Oacc[nt][1] *= corr0;
            Oacc[nt][2] *= corr1; Oacc[nt][3] *= corr1;
        }

        __syncthreads();
        if (kt + 1 < 8) {
            size_t ebn = ebase0 + (kt + 1) * 128;
            #pragma unroll
            for (int i = 0; i < 16; i++) {
                int id = tid + i * 256;
                int r = id >> 5, c = id & 31;
                CP16(sb + EDGE_OFF + r * EDGE_PITCH + c * 16, edge + ebn + (size_t)r * LL + c * 4);
            }
            CP_COMMIT();
        }

        #pragma unroll
        for (int j = 0; j < 8; j++) {
            uint32_t ah[4], al[4];
            pack_split(S[2 * j][0],     S[2 * j][1],     ah[0], al[0]);
            pack_split(S[2 * j][2],     S[2 * j][3],     ah[1], al[1]);
            pack_split(S[2 * j + 1][0], S[2 * j + 1][1], ah[2], al[2]);
            pack_split(S[2 * j + 1][2], S[2 * j + 1][3], ah[3], al[3]);
            uint32_t vh[4][4], vl[4][4];
            #pragma unroll
            for (int dg = 0; dg < 4; dg++) {
                uint32_t off = SWZ128((uint32_t)((j * 16 + rowV) * 128 + (dg * 16 + dcV) * 2));
                LDSM4T(vh[dg], tb + 32768 + off);
                LDSM4T(vl[dg], tb + 49152 + off);
            }
            #pragma unroll
            for (int dg = 0; dg < 4; dg++) {
                MMA16816(Oacc[2 * dg],     ah, vh[dg][0], vh[dg][1]);
                MMA16816(Oacc[2 * dg + 1], ah, vh[dg][2], vh[dg][3]);
            }
            #pragma unroll
            for (int dg = 0; dg < 4; dg++) {
                MMA16816(Oacc[2 * dg],     ah, vl[dg][0], vl[dg][1]);
                MMA16816(Oacc[2 * dg + 1], ah, vl[dg][2], vl[dg][3]);
            }
            #pragma unroll
            for (int dg = 0; dg < 4; dg++) {
                MMA16816(Oacc[2 * dg],     al, vh[dg][0], vh[dg][1]);
                MMA16816(Oacc[2 * dg + 1], al, vh[dg][2], vh[dg][3]);
            }
        }
    }

    float inv0 = 1.f / l_run[0], inv1 = 1.f / l_run[1];
    int r0 = q0 + wr * 16 + g;
    #pragma unroll
    for (int nt = 0; nt < 8; nt++) {
        int d = hh * HDIM + nt * 8 + tg * 2;
        size_t o0 = ((size_t)r0 * BB + b) * DD + d;
        size_t o1 = ((size_t)(r0 + 8) * BB + b) * DD + d;
        uint32_t hi, lo;
        pack_split(Oacc[nt][0] * inv0, Oacc[nt][1] * inv0, hi, lo);
        *(uint32_t*)&attn_hi[o0] = hi;
        *(uint32_t*)&attn_lo[o0] = lo;
        pack_split(Oacc[nt][2] * inv1, Oacc[nt][3] * inv1, hi, lo);
        *(uint32_t*)&attn_hi[o1] = hi;
        *(uint32_t*)&attn_lo[o1] = lo;
    }
}

// ---------------- host orchestration ----------------------------------------
extern "C" void kernel_launch(void* const* d_in, const int* in_sizes, int n_in,
                              void* d_out, int out_size) {
    const float* x         = (const float*)d_in[0];
    const float* edge      = (const float*)d_in[1];
    const float* in_proj_w = (const float*)d_in[2];
    const float* in_proj_b = (const float*)d_in[3];
    const float* out_proj_w= (const float*)d_in[4];
    const float* out_proj_b= (const float*)d_in[5];
    const float* lin1_w    = (const float*)d_in[6];
    const float* lin1_b    = (const float*)d_in[7];
    const float* lin2_w    = (const float*)d_in[8];
    const float* lin2_b    = (const float*)d_in[9];
    const float* norm1_w   = (const float*)d_in[10];
    const float* norm1_b   = (const float*)d_in[11];
    const float* norm2_w   = (const float*)d_in[12];
    const float* norm2_b   = (const float*)d_in[13];

    float* out_x    = (float*)d_out;
    float* edge_out = (float*)d_out + (size_t)NROWS * DD;

    __nv_bfloat16 *h_hi, *h_lo, *qkv_hi, *qkv_lo, *attn_hi, *attn_lo;
    __nv_bfloat16 *h2_hi, *h2_lo, *ff_hi, *ff_lo;
    __nv_bfloat16 *w1h, *w1l, *w2h, *w2l, *w3h, *w3l, *w4h, *w4l;
    float *x1;
    cudaGetSymbolAddress((void**)&h_hi, g_h_hi);   cudaGetSymbolAddress((void**)&h_lo, g_h_lo);
    cudaGetSymbolAddress((void**)&qkv_hi, g_qkv_hi); cudaGetSymbolAddress((void**)&qkv_lo, g_qkv_lo);
    cudaGetSymbolAddress((void**)&attn_hi, g_attn_hi); cudaGetSymbolAddress((void**)&attn_lo, g_attn_lo);
    cudaGetSymbolAddress((void**)&x1, g_x1);
    cudaGetSymbolAddress((void**)&h2_hi, g_h2_hi); cudaGetSymbolAddress((void**)&h2_lo, g_h2_lo);
    cudaGetSymbolAddress((void**)&ff_hi, g_ff_hi); cudaGetSymbolAddress((void**)&ff_lo, g_ff_lo);
    cudaGetSymbolAddress((void**)&w1h, g_w1_hi); cudaGetSymbolAddress((void**)&w1l, g_w1_lo);
    cudaGetSymbolAddress((void**)&w2h, g_w2_hi); cudaGetSymbolAddress((void**)&w2l, g_w2_lo);
    cudaGetSymbolAddress((void**)&w3h, g_w3_hi); cudaGetSymbolAddress((void**)&w3l, g_w3_lo);
    cudaGetSymbolAddress((void**)&w4h, g_w4_hi); cudaGetSymbolAddress((void**)&w4l, g_w4_lo);

    int gemm_smem = 2 * GB_STRIDE;                 // 65536
    cudaFuncSetAttribute(gemm_mma, cudaFuncAttributeMaxDynamicSharedMemorySize, gemm_smem);
    int attn_smem = EDGE_OFF + 128 * EDGE_PITCH;   // 231424
    cudaFuncSetAttribute(attn_mma, cudaFuncAttributeMaxDynamicSharedMemorySize, attn_smem);

    // 0. split all weights to bf16 hi/lo (one launch)
    split_all_kernel<<<(W1N + W2N + W3N + W4N) / 1024, 256>>>(
        in_proj_w, out_proj_w, lin1_w, lin2_w,
        w1h, w1l, w2h, w2l, w3h, w3l, w4h, w4l);

    // 1. h = LN1(x) -> bf16 hi/lo
    ln_split_kernel<<<NROWS, 256>>>(x, norm1_w, norm1_b, h_hi, h_lo);

    // 2. qkv = h @ in_proj_w^T + b -> bf16 hi/lo (EPI 3)
    gemm_mma<<<dim3(QKVW / 128, NROWS / 128), 256, gemm_smem>>>(
        h_hi, h_lo, w1h, w1l, in_proj_b, nullptr, nullptr, qkv_hi, qkv_lo,
        NROWS, QKVW, DD, 3);

    // 3. attention: edge_out + attn hi/lo (fully pipelined)
    attn_mma<<<dim3(8, 64), 256, attn_smem>>>(qkv_hi, qkv_lo, edge, edge_out,
                                              attn_hi, attn_lo);

    // 4. x1 = x + attn @ out_proj_w^T + b
    gemm_mma<<<dim3(DD / 128, NROWS / 128), 256, gemm_smem>>>(
        attn_hi, attn_lo, w2h, w2l, out_proj_b, x, x1, nullptr, nullptr,
        NROWS, DD, DD, 2);

    // 5. h2 = LN2(x1) -> bf16 hi/lo
    ln_split_kernel<<<NROWS, 256>>>(x1, norm2_w, norm2_b, h2_hi, h2_lo);

    // 6. ff = gelu(h2 @ lin1_w^T + b) -> bf16 hi/lo
    gemm_mma<<<dim3(DFF_ / 128, NROWS / 128), 256, gemm_smem>>>(
        h2_hi, h2_lo, w3h, w3l, lin1_b, nullptr, nullptr, ff_hi, ff_lo,
        NROWS, DFF_, DD, 1);

    // 7. out_x = x1 + ff @ lin2_w^T + b
    gemm_mma<<<dim3(DD / 128, NROWS / 128), 256, gemm_smem>>>(
        ff_hi, ff_lo, w4h, w4l, lin2_b, x1, out_x, nullptr, nullptr,
        NROWS, DD, DFF_, 2);
}

// round 16
// speedup vs baseline: 2.2318x; 2.2318x over previous
#include <cuda_runtime.h>
#include <cuda_fp16.h>
#include <math.h>
#include <stdint.h>

// Problem constants
#define LL 1024
#define BB 4
#define DD 1024
#define HH 16
#define HDIM 64
#define DFF_ 4096
#define NROWS 4096        // L*B
#define QKVW 3072         // 3*D

// ---------------- scratch (device globals; no allocation allowed) ------------
__device__ __half g_h_h[(size_t)NROWS * DD];
__device__ __half g_qkv_h[(size_t)NROWS * QKVW];
__device__ __half g_attn_h[(size_t)NROWS * DD];
__device__ float  g_x1[(size_t)NROWS * DD];
__device__ __half g_h2_h[(size_t)NROWS * DD];
__device__ __half g_ff_h[(size_t)NROWS * DFF_];
__device__ __half g_w1[(size_t)QKVW * DD];
__device__ __half g_w2[(size_t)DD * DD];
__device__ __half g_w3[(size_t)DFF_ * DD];
__device__ __half g_w4[(size_t)DD * DFF_];

// ---------------- helpers ----------------------------------------------------
__device__ __forceinline__ uint32_t smem_u32(const void* p) {
    uint32_t a;
    asm("{ .reg .u64 t; cvta.to.shared.u64 t, %1; cvt.u32.u64 %0, t; }" : "=r"(a) : "l"(p));
    return a;
}
#define SWZ128(o) ((o) ^ (((o) >> 3) & 0x70))

#define CP16(s, g) asm volatile("cp.async.cg.shared.global [%0], [%1], 16;\n" :: "r"(s), "l"(g) : "memory")
#define CP_COMMIT() asm volatile("cp.async.commit_group;\n" ::: "memory")
#define CP_WAIT1()  asm volatile("cp.async.wait_group 1;\n" ::: "memory")
#define CP_WAIT0()  asm volatile("cp.async.wait_group 0;\n" ::: "memory")

#define LDSM4(r, addr) \
    asm volatile("ldmatrix.sync.aligned.m8n8.x4.shared.b16 {%0,%1,%2,%3}, [%4];" \
        : "=r"((r)[0]), "=r"((r)[1]), "=r"((r)[2]), "=r"((r)[3]) : "r"(addr))
#define LDSM4T(r, addr) \
    asm volatile("ldmatrix.sync.aligned.m8n8.x4.trans.shared.b16 {%0,%1,%2,%3}, [%4];" \
        : "=r"((r)[0]), "=r"((r)[1]), "=r"((r)[2]), "=r"((r)[3]) : "r"(addr))

#define MMAH(d, a, b0, b1) \
    asm volatile("mma.sync.aligned.m16n8k16.row.col.f32.f16.f16.f32 " \
        "{%0,%1,%2,%3}, {%4,%5,%6,%7}, {%8,%9}, {%0,%1,%2,%3};" \
        : "+f"((d)[0]), "+f"((d)[1]), "+f"((d)[2]), "+f"((d)[3]) \
        : "r"((a)[0]), "r"((a)[1]), "r"((a)[2]), "r"((a)[3]), "r"(b0), "r"(b1))

__device__ __forceinline__ uint32_t pack_h2(float a, float b) {
    __half2 h = __floats2half2_rn(a, b);
    return *reinterpret_cast<uint32_t*>(&h);
}

// ---------------- merged weight convert: fp32 -> fp16, all 4 weights ---------
#define W1N (QKVW * DD)
#define W2N (DD * DD)
#define W3N (DFF_ * DD)
#define W4N (DD * DFF_)
__global__ void conv_all_kernel(const float* __restrict__ s1, const float* __restrict__ s2,
                                const float* __restrict__ s3, const float* __restrict__ s4,
                                __half* __restrict__ d1, __half* __restrict__ d2,
                                __half* __restrict__ d3, __half* __restrict__ d4) {
    int i = (blockIdx.x * 256 + threadIdx.x) * 4;
    const float* src; __half* dst;
    if (i < W1N)                   { src = s1; dst = d1; }
    else if (i < W1N + W2N)        { i -= W1N; src = s2; dst = d2; }
    else if (i < W1N + W2N + W3N)  { i -= W1N + W2N; src = s3; dst = d3; }
    else                           { i -= W1N + W2N + W3N; src = s4; dst = d4; }
    float4 v = *(const float4*)(src + i);
    uint32_t p0 = pack_h2(v.x, v.y), p1 = pack_h2(v.z, v.w);
    *(uint32_t*)&dst[i]     = p0;
    *(uint32_t*)&dst[i + 2] = p1;
}

// ---------------- LayerNorm -> fp16 ------------------------------------------
__global__ void ln_h_kernel(const float* __restrict__ X, const float* __restrict__ w,
                            const float* __restrict__ b, __half* __restrict__ Y) {
    int row = blockIdx.x;
    int tid = threadIdx.x;
    const float* xr = X + (size_t)row * DD;
    float v0 = xr[tid], v1 = xr[tid + 256], v2 = xr[tid + 512], v3 = xr[tid + 768];
    float s = v0 + v1 + v2 + v3;
    float s2 = v0 * v0 + v1 * v1 + v2 * v2 + v3 * v3;
    #pragma unroll
    for (int off = 16; off; off >>= 1) {
        s  += __shfl_xor_sync(0xffffffffu, s, off);
        s2 += __shfl_xor_sync(0xffffffffu, s2, off);
    }
    __shared__ float sh[16];
    __shared__ float smean, sinv;
    int wid = tid >> 5, lid = tid & 31;
    if (lid == 0) { sh[wid] = s; sh[wid + 8] = s2; }
    __syncthreads();
    if (wid == 0) {
        float a  = (lid < 8) ? sh[lid] : 0.f;
        float a2 = (lid < 8) ? sh[lid + 8] : 0.f;
        #pragma unroll
        for (int off = 4; off; off >>= 1) {
            a  += __shfl_xor_sync(0xffffffffu, a, off, 8);
            a2 += __shfl_xor_sync(0xffffffffu, a2, off, 8);
        }
        if (lid == 0) {
            float mean = a * (1.f / DD);
            float var = a2 * (1.f / DD) - mean * mean;
            smean = mean;
            sinv = rsqrtf(var + 1e-5f);
        }
    }
    __syncthreads();
    float mean = smean, inv = sinv;
    size_t base = (size_t)row * DD;
    #pragma unroll
    for (int q = 0; q < 4; q++) {
        int c = tid + q * 256;
        float v = (q == 0 ? v0 : q == 1 ? v1 : q == 2 ? v2 : v3);
        Y[base + c] = __float2half((v - mean) * inv * w[c] + b[c]);
    }
}

// ---------------- mma.sync fp16 GEMM, CTA 128x128, K-chunk 64, 2 CTA/SM ------
// EPI: 1 = gelu(+bias) -> fp16 ; 2 = +bias+Res -> fp32 ; 3 = +bias -> fp16
// Per-chunk smem: A 16K | B 16K = 32K; 2 buffers = 64K -> 2 CTAs/SM.
#define GB_STRIDE 32768
__global__ void __launch_bounds__(256, 2)
gemm_mma(const __half* __restrict__ A, const __half* __restrict__ B,
         const float* __restrict__ bias, const float* __restrict__ Res,
         float* __restrict__ OutF, __half* __restrict__ OutH,
         int M, int N, int K, int EPI) {
    extern __shared__ __align__(1024) char smem[];
    uint32_t sb = smem_u32(smem);
    int tid = threadIdx.x;
    int w = tid >> 5, lane = tid & 31;
    int wm = w & 3, wn = w >> 2;            // 4 m-strips(32) x 2 n-strips(64)
    int m0 = blockIdx.y * 128, n0 = blockIdx.x * 128;
    const int nc = K >> 6;

    float acc[2][8][4];
    #pragma unroll
    for (int i = 0; i < 2; i++)
        #pragma unroll
        for (int j = 0; j < 8; j++)
            #pragma unroll
            for (int r = 0; r < 4; r++) acc[i][j][r] = 0.f;

    int rowA = (lane & 7) + (((lane >> 3) & 1) << 3);
    int kbA  = ((lane >> 4) & 1) << 4;
    int rowB = (lane & 7) + (((lane >> 4) & 1) << 3);
    int kbB  = ((lane >> 3) & 1) << 4;

    // chunk loader: 128x64 A + 128x64 B fp16; 128B rows, SW128
    #define GLOAD(buf, k0)                                                       \
    {                                                                            \
        uint32_t bA = sb + (buf) * GB_STRIDE;                                    \
        _Pragma("unroll")                                                        \
        for (int i = 0; i < 4; i++) {                                            \
            int id = tid + (i << 8);                                             \
            int row = id >> 3, c = id & 7;                                       \
            uint32_t so = SWZ128((uint32_t)(row * 128 + c * 16));                \
            CP16(bA + so,         A + (size_t)(m0 + row) * K + (k0) + c * 8);    \
            CP16(bA + 16384 + so, B + (size_t)(n0 + row) * K + (k0) + c * 8);    \
        }                                                                        \
    }

    GLOAD(0, 0);
    CP_COMMIT();

    for (int kc = 0; kc < nc; kc++) {
        int b = kc & 1;
        if (kc + 1 < nc) {
            if (kc >= 1) __syncthreads();
            GLOAD(b ^ 1, (kc + 1) << 6);
            CP_COMMIT();
            CP_WAIT1();
        } else {
            CP_WAIT0();
        }
        __syncthreads();

        uint32_t tb = sb + b * GB_STRIDE;
        #pragma unroll
        for (int ks = 0; ks < 4; ks++) {
            int kb = ks * 32;
            uint32_t ah[2][4], bh[4][4];
            #pragma unroll
            for (int mt = 0; mt < 2; mt++) {
                uint32_t off = SWZ128((uint32_t)((wm * 32 + mt * 16 + rowA) * 128 + kb + kbA));
                LDSM4(ah[mt], tb + off);
            }
            #pragma unroll
            for (int p = 0; p < 4; p++) {
                uint32_t off = SWZ128((uint32_t)((wn * 64 + p * 16 + rowB) * 128 + kb + kbB));
                LDSM4(bh[p], tb + 16384 + off);
            }
            #pragma unroll
            for (int mt = 0; mt < 2; mt++)
                #pragma unroll
                for (int nt = 0; nt < 8; nt++) {
                    int p = nt >> 1, h = (nt & 1) * 2;
                    MMAH(acc[mt][nt], ah[mt], bh[p][h], bh[p][h + 1]);
                }
        }
    }

    int gr = lane >> 2, tg = lane & 3;
    #pragma unroll
    for (int mt = 0; mt < 2; mt++) {
        #pragma unroll
        for (int nt = 0; nt < 8; nt++) {
            int r0 = m0 + wm * 32 + mt * 16 + gr;
            int c  = n0 + wn * 64 + nt * 8 + tg * 2;
            float b0 = __ldg(&bias[c]), b1 = __ldg(&bias[c + 1]);
            float v00 = acc[mt][nt][0] + b0, v01 = acc[mt][nt][1] + b1;
            float v10 = acc[mt][nt][2] + b0, v11 = acc[mt][nt][3] + b1;
            size_t o0 = (size_t)r0 * N + c;
            size_t o1 = (size_t)(r0 + 8) * N + c;
            if (EPI == 1 || EPI == 3) {
                if (EPI == 1) {
                    v00 = 0.5f * v00 * (1.f + erff(v00 * 0.70710678118654752f));
                    v01 = 0.5f * v01 * (1.f + erff(v01 * 0.70710678118654752f));
                    v10 = 0.5f * v10 * (1.f + erff(v10 * 0.70710678118654752f));
                    v11 = 0.5f * v11 * (1.f + erff(v11 * 0.70710678118654752f));
                }
                *(uint32_t*)&OutH[o0] = pack_h2(v00, v01);
                *(uint32_t*)&OutH[o1] = pack_h2(v10, v11);
            } else {
                if (EPI == 2) {
                    float2 r0v = *(const float2*)&Res[o0];
                    float2 r1v = *(const float2*)&Res[o1];
                    v00 += r0v.x; v01 += r0v.y; v10 += r1v.x; v11 += r1v.y;
                }
                *(float2*)&OutF[o0] = make_float2(v00, v01);
                *(float2*)&OutF[o1] = make_float2(v10, v11);
            }
        }
    }
    #undef GLOAD
}

// ---------------- Flash attention, fp16 mma.sync, fully double-buffered ------
// CTA: 128 q-rows of one bh; 8 warps x 16 rows; key tiles of 128.
// smem: Q 16K | KV 2x32K | edge 2x66K = 212K (1 CTA/SM).
#define KV_OFF   16384
#define KV_SZ    32768
#define EDGE_OFF 81920
#define EDGE_PITCH 528
#define EDGE_SZ  (128 * EDGE_PITCH)
__global__ void __launch_bounds__(256, 1)
attn_mma(const __half* __restrict__ qkv, const float* __restrict__ edge,
         float* __restrict__ edge_out, __half* __restrict__ attn_o) {
    extern __shared__ __align__(1024) char smem[];
    uint32_t sb = smem_u32(smem);
    int bh = blockIdx.y;
    int q0 = blockIdx.x * 128;
    int b = bh >> 4, hh = bh & 15;
    int tid = threadIdx.x, lane = tid & 31, wr = tid >> 5;
    int g = lane >> 2, tg = lane & 3;

    size_t ebase0 = ((size_t)bh << 20) + (size_t)q0 * LL;

    // prologue: Q + KV tile 0 + edge tile 0, one group
    #pragma unroll
    for (int i = 0; i < 4; i++) {
        int id = tid + i * 256;
        int r = id >> 3, c = id & 7;
        uint32_t so = SWZ128((uint32_t)(r * 128 + c * 16));
        CP16(sb + so, qkv + ((size_t)(q0 + r) * BB + b) * QKVW + hh * HDIM + c * 8);
    }
    #pragma unroll
    for (int i = 0; i < 8; i++) {
        int id = tid + i * 256;
        int a = id >> 10;                      // 0 = K, 1 = V
        int r = (id >> 3) & 127, c = id & 7;
        uint32_t so = SWZ128((uint32_t)(r * 128 + c * 16));
        size_t off = ((size_t)r * BB + b) * QKVW + hh * HDIM + c * 8 + (a ? 2 * DD : DD);
        CP16(sb + KV_OFF + a * 16384 + so, qkv + off);
    }
    #pragma unroll
    for (int i = 0; i < 16; i++) {
        int id = tid + i * 256;
        int r = id >> 5, c = id & 31;
        CP16(sb + EDGE_OFF + r * EDGE_PITCH + c * 16, edge + ebase0 + (size_t)r * LL + c * 4);
    }
    CP_COMMIT(); CP_WAIT0(); __syncthreads();

    int rowA = (lane & 7) + (((lane >> 3) & 1) << 3);
    int kbA  = ((lane >> 4) & 1) << 4;
    uint32_t qa[4][4];
    #pragma unroll
    for (int ks = 0; ks < 4; ks++) {
        uint32_t off = SWZ128((uint32_t)((wr * 16 + rowA) * 128 + ks * 32 + kbA));
        LDSM4(qa[ks], sb + off);
    }

    float m_run[2] = {-1e30f, -1e30f}, l_run[2] = {0.f, 0.f};
    float Oacc[8][4];
    #pragma unroll
    for (int i = 0; i < 8; i++)
        #pragma unroll
        for (int r = 0; r < 4; r++) Oacc[i][r] = 0.f;

    int rowB = (lane & 7) + (((lane >> 4) & 1) << 3);
    int kbB  = ((lane >> 3) & 1) << 4;
    int rowV = lane & 15, dcV = ((lane >> 4) & 1) * 8;
    int erow = (wr * 16 + g) * EDGE_PITCH + tg * 8;

    for (int kt = 0; kt < 8; kt++) {
        int bf = kt & 1;
        if (kt > 0) { CP_WAIT0(); }
        __syncthreads();     // warps done with buffers bf^1 (compute kt-1)

        if (kt + 1 < 8) {    // prefetch KV+edge tile kt+1 into bf^1 buffers
            int k0n = (kt + 1) * 128;
            uint32_t kvb = sb + KV_OFF + (bf ^ 1) * KV_SZ;
            #pragma unroll
            for (int i = 0; i < 8; i++) {
                int id = tid + i * 256;
                int a = id >> 10;
                int r = (id >> 3) & 127, c = id & 7;
                uint32_t so = SWZ128((uint32_t)(r * 128 + c * 16));
                size_t off = ((size_t)(k0n + r) * BB + b) * QKVW + hh * HDIM + c * 8
                           + (a ? 2 * DD : DD);
                CP16(kvb + a * 16384 + so, qkv + off);
            }
            uint32_t edb = sb + EDGE_OFF + (bf ^ 1) * EDGE_SZ;
            size_t ebn = ebase0 + (size_t)(kt + 1) * 128;
            #pragma unroll
            for (int i = 0; i < 16; i++) {
                int id = tid + i * 256;
                int r = id >> 5, c = id & 31;
                CP16(edb + r * EDGE_PITCH + c * 16, edge + ebn + (size_t)r * LL + c * 4);
            }
            CP_COMMIT();
        }

        uint32_t tb = sb + KV_OFF + bf * KV_SZ;
        uint32_t eb = sb + EDGE_OFF + bf * EDGE_SZ;
        int k0 = kt * 128;

        // S = Q K^T (single fp16 pass)
        float S[16][4];
        #pragma unroll
        for (int i = 0; i < 16; i++)
            #pragma unroll
            for (int r = 0; r < 4; r++) S[i][r] = 0.f;
        #pragma unroll
        for (int ks = 0; ks < 4; ks++) {
            #pragma unroll
            for (int j = 0; j < 8; j++) {
                uint32_t kh[4];
                uint32_t off = SWZ128((uint32_t)((j * 16 + rowB) * 128 + ks * 32 + kbB));
                LDSM4(kh, tb + off);
                MMAH(S[2 * j],     qa[ks], kh[0], kh[1]);
                MMAH(S[2 * j + 1], qa[ks], kh[2], kh[3]);
            }
        }

        // t = S/8 + edge (smem); stream to edge_out
        size_t ebaseg = ((size_t)bh << 20) + (size_t)(q0 + wr * 16 + g) * LL + k0 + tg * 2;
        #pragma unroll
        for (int nt = 0; nt < 16; nt++) {
            float2 ea = *(const float2*)(smem + (eb - sb) + erow + nt * 32);
            float2 ebv = *(const float2*)(smem + (eb - sb) + erow + nt * 32 + 8 * EDGE_PITCH);
            S[nt][0] = fmaf(S[nt][0], 0.125f, ea.x);
            S[nt][1] = fmaf(S[nt][1], 0.125f, ea.y);
            S[nt][2] = fmaf(S[nt][2], 0.125f, ebv.x);
            S[nt][3] = fmaf(S[nt][3], 0.125f, ebv.y);
            size_t e0 = ebaseg + nt * 8;
            *(float2*)&edge_out[e0]          = make_float2(S[nt][0], S[nt][1]);
            *(float2*)&edge_out[e0 + 8 * LL] = make_float2(S[nt][2], S[nt][3]);
        }

        // online softmax
        float mx0 = -1e30f, mx1 = -1e30f;
        #pragma unroll
        for (int nt = 0; nt < 16; nt++) {
            mx0 = fmaxf(mx0, fmaxf(S[nt][0], S[nt][1]));
            mx1 = fmaxf(mx1, fmaxf(S[nt][2], S[nt][3]));
        }
        mx0 = fmaxf(mx0, __shfl_xor_sync(0xffffffffu, mx0, 1));
        mx0 = fmaxf(mx0, __shfl_xor_sync(0xffffffffu, mx0, 2));
        mx1 = fmaxf(mx1, __shfl_xor_sync(0xffffffffu, mx1, 1));
        mx1 = fmaxf(mx1, __shfl_xor_sync(0xffffffffu, mx1, 2));
        float mn0 = fmaxf(m_run[0], mx0), mn1 = fmaxf(m_run[1], mx1);
        float corr0 = __expf(m_run[0] - mn0), corr1 = __expf(m_run[1] - mn1);
        float s0 = 0.f, s1 = 0.f;
        #pragma unroll
        for (int nt = 0; nt < 16; nt++) {
            S[nt][0] = __expf(S[nt][0] - mn0); s0 += S[nt][0];
            S[nt][1] = __expf(S[nt][1] - mn0); s0 += S[nt][1];
            S[nt][2] = __expf(S[nt][2] - mn1); s1 += S[nt][2];
            S[nt][3] = __expf(S[nt][3] - mn1); s1 += S[nt][3];
        }
        s0 += __shfl_xor_sync(0xffffffffu, s0, 1);
        s0 += __shfl_xor_sync(0xffffffffu, s0, 2);
        s1 += __shfl_xor_sync(0xffffffffu, s1, 1);
        s1 += __shfl_xor_sync(0xffffffffu, s1, 2);
        l_run[0] = l_run[0] * corr0 + s0; m_run[0] = mn0;
        l_run[1] = l_run[1] * corr1 + s1; m_run[1] = mn1;
        #pragma unroll
        for (int nt = 0; nt < 8; nt++) {
            Oacc[nt][0] *= corr0; Oacc[nt][1] *= corr0;
            Oacc[nt][2] *= corr1; Oacc[nt][3] *= corr1;
        }

        // O += P V (single fp16 pass)
        #pragma unroll
        for (int j = 0; j < 8; j++) {
            uint32_t ah[4];
            ah[0] = pack_h2(S[2 * j][0],     S[2 * j][1]);
            ah[1] = pack_h2(S[2 * j][2],     S[2 * j][3]);
            ah[2] = pack_h2(S[2 * j + 1][0], S[2 * j + 1][1]);
            ah[3] = pack_h2(S[2 * j + 1][2], S[2 * j + 1][3]);
            uint32_t vh[4][4];
            #pragma unroll
            for (int dg = 0; dg < 4; dg++) {
                uint32_t off = SWZ128((uint32_t)((j * 16 + rowV) * 128 + (dg * 16 + dcV) * 2));
                LDSM4T(vh[dg], tb + 16384 + off);
            }
            #pragma unroll
            for (int dg = 0; dg < 4; dg++) {
                MMAH(Oacc[2 * dg],     ah, vh[dg][0], vh[dg][1]);
                MMAH(Oacc[2 * dg + 1], ah, vh[dg][2], vh[dg][3]);
            }
        }
    }

    // finalize: O/l -> fp16 at merged [l*B+b, D] layout
    float inv0 = 1.f / l_run[0], inv1 = 1.f / l_run[1];
    int r0 = q0 + wr * 16 + g;
    #pragma unroll
    for (int nt = 0; nt < 8; nt++) {
        int d = hh * HDIM + nt * 8 + tg * 2;
        size_t o0 = ((size_t)r0 * BB + b) * DD + d;
        size_t o1 = ((size_t)(r0 + 8) * BB + b) * DD + d;
        *(uint32_t*)&attn_o[o0] = pack_h2(Oacc[nt][0] * inv0, Oacc[nt][1] * inv0);
        *(uint32_t*)&attn_o[o1] = pack_h2(Oacc[nt][2] * inv1, Oacc[nt][3] * inv1);
    }
}

// ---------------- host orchestration ----------------------------------------
extern "C" void kernel_launch(void* const* d_in, const int* in_sizes, int n_in,
                              void* d_out, int out_size) {
    const float* x         = (const float*)d_in[0];
    const float* edge      = (const float*)d_in[1];
    const float* in_proj_w = (const float*)d_in[2];
    const float* in_proj_b = (const float*)d_in[3];
    const float* out_proj_w= (const float*)d_in[4];
    const float* out_proj_b= (const float*)d_in[5];
    const float* lin1_w    = (const float*)d_in[6];
    const float* lin1_b    = (const float*)d_in[7];
    const float* lin2_w    = (const float*)d_in[8];
    const float* lin2_b    = (const float*)d_in[9];
    const float* norm1_w   = (const float*)d_in[10];
    const float* norm1_b   = (const float*)d_in[11];
    const float* norm2_w   = (const float*)d_in[12];
    const float* norm2_b   = (const float*)d_in[13];

    float* out_x    = (float*)d_out;
    float* edge_out = (float*)d_out + (size_t)NROWS * DD;

    __half *h_h, *qkv_h, *attn_h, *h2_h, *ff_h, *w1, *w2, *w3, *w4;
    float *x1;
    cudaGetSymbolAddress((void**)&h_h, g_h_h);
    cudaGetSymbolAddress((void**)&qkv_h, g_qkv_h);
    cudaGetSymbolAddress((void**)&attn_h, g_attn_h);
    cudaGetSymbolAddress((void**)&x1, g_x1);
    cudaGetSymbolAddress((void**)&h2_h, g_h2_h);
    cudaGetSymbolAddress((void**)&ff_h, g_ff_h);
    cudaGetSymbolAddress((void**)&w1, g_w1);
    cudaGetSymbolAddress((void**)&w2, g_w2);
    cudaGetSymbolAddress((void**)&w3, g_w3);
    cudaGetSymbolAddress((void**)&w4, g_w4);

    int gemm_smem = 2 * GB_STRIDE;                 // 65536
    cudaFuncSetAttribute(gemm_mma, cudaFuncAttributeMaxDynamicSharedMemorySize, gemm_smem);
    int attn_smem = EDGE_OFF + 2 * EDGE_SZ;        // 217088
    cudaFuncSetAttribute(attn_mma, cudaFuncAttributeMaxDynamicSharedMemorySize, attn_smem);

    // 0. convert all weights to fp16 (one launch)
    conv_all_kernel<<<(W1N + W2N + W3N + W4N) / 1024, 256>>>(
        in_proj_w, out_proj_w, lin1_w, lin2_w, w1, w2, w3, w4);

    // 1. h = LN1(x) -> fp16
    ln_h_kernel<<<NROWS, 256>>>(x, norm1_w, norm1_b, h_h);

    // 2. qkv = h @ in_proj_w^T + b -> fp16 (EPI 3)
    gemm_mma<<<dim3(QKVW / 128, NROWS / 128), 256, gemm_smem>>>(
        h_h, w1, in_proj_b, nullptr, nullptr, qkv_h, NROWS, QKVW, DD, 3);

    // 3. attention: edge_out + attn fp16
    attn_mma<<<dim3(8, 64), 256, attn_smem>>>(qkv_h, edge, edge_out, attn_h);

    // 4. x1 = x + attn @ out_proj_w^T + b (fp32)
    gemm_mma<<<dim3(DD / 128, NROWS / 128), 256, gemm_smem>>>(
        attn_h, w2, out_proj_b, x, x1, nullptr, NROWS, DD, DD, 2);

    // 5. h2 = LN2(x1) -> fp16
    ln_h_kernel<<<NROWS, 256>>>(x1, norm2_w, norm2_b, h2_h);

    // 6. ff = gelu(h2 @ lin1_w^T + b) -> fp16
    gemm_mma<<<dim3(DFF_ / 128, NROWS / 128), 256, gemm_smem>>>(
        h2_h, w3, lin1_b, nullptr, nullptr, ff_h, NROWS, DFF_, DD, 1);

    // 7. out_x = x1 + ff @ lin2_w^T + b (fp32)
    gemm_mma<<<dim3(DD / 128, NROWS / 128), 256, gemm_smem>>>(
        ff_h, w4, lin2_b, x1, out_x, nullptr, NROWS, DD, DFF_, 2);
}